// round 1
// baseline (speedup 1.0000x reference)
#include <cuda_runtime.h>
#include <cstdint>

// TopK keep: zero all but the K largest entries per row (last axis).
// x: f32[4, 4096, 4096] -> rows = 16384, d = 4096, K = 512.
//
// One CTA per row. Each thread holds 16 contiguous elements in registers as
// order-preserving uint32 keys. 32-step binary search on key value finds the
// exact K-th largest key; a stable rank scan resolves ties lowest-index-first
// (matching jax.lax.top_k / torch.topk semantics).

#define D_DIM       4096
#define K_KEEP      512
#define NTHREADS    256
#define PER_THREAD  16   // D_DIM / NTHREADS

// monotonic float->uint mapping: preserves total order of floats
__device__ __forceinline__ unsigned f2k(float f) {
    unsigned u = __float_as_uint(f);
    return (u & 0x80000000u) ? ~u : (u | 0x80000000u);
}
__device__ __forceinline__ float k2f(unsigned k) {
    return __uint_as_float((k & 0x80000000u) ? (k ^ 0x80000000u) : ~k);
}

// block-wide sum of per-thread uint, broadcast to all threads.
// sh must have >= 33 uints. Two __syncthreads per call.
__device__ __forceinline__ unsigned block_reduce_bcast(unsigned val,
                                                       unsigned* sh,
                                                       int lane, int warp) {
#pragma unroll
    for (int o = 16; o > 0; o >>= 1)
        val += __shfl_down_sync(0xFFFFFFFFu, val, o);
    if (lane == 0) sh[warp] = val;
    __syncthreads();
    if (warp == 0) {
        unsigned v = (lane < (NTHREADS / 32)) ? sh[lane] : 0u;
#pragma unroll
        for (int o = 4; o > 0; o >>= 1)
            v += __shfl_down_sync(0xFFFFFFFFu, v, o);
        if (lane == 0) sh[32] = v;
    }
    __syncthreads();
    return sh[32];
}

__global__ __launch_bounds__(NTHREADS)
void topk_keep_kernel(const float* __restrict__ x, float* __restrict__ out) {
    __shared__ unsigned sh_red[34];
    __shared__ unsigned sh_scan[NTHREADS];

    const int tid  = threadIdx.x;
    const int lane = tid & 31;
    const int warp = tid >> 5;
    const size_t row_base = (size_t)blockIdx.x * D_DIM;

    // ---- load 16 contiguous elements per thread as keys (4x float4) ----
    const float4* xr = reinterpret_cast<const float4*>(x + row_base) + tid * 4;
    unsigned key[PER_THREAD];
#pragma unroll
    for (int j = 0; j < 4; ++j) {
        float4 v = xr[j];
        key[j * 4 + 0] = f2k(v.x);
        key[j * 4 + 1] = f2k(v.y);
        key[j * 4 + 2] = f2k(v.z);
        key[j * 4 + 3] = f2k(v.w);
    }

    // ---- binary search: T = largest v with count(key >= v) >= K ----
    unsigned lo = 0u, hi = 0xFFFFFFFFu;
#pragma unroll 1
    while (lo < hi) {
        unsigned mid = lo + ((hi - lo) >> 1) + ((hi - lo) & 1u); // ceil midpoint
        unsigned cnt = 0;
#pragma unroll
        for (int i = 0; i < PER_THREAD; ++i)
            cnt += (key[i] >= mid) ? 1u : 0u;
        unsigned total = block_reduce_bcast(cnt, sh_red, lane, warp);
        if (total >= K_KEEP) lo = mid; else hi = mid - 1u;
    }
    const unsigned T = lo;  // exact K-th largest key in this row

    // ---- count strictly-greater, derive how many ==T to keep ----
    unsigned cgt = 0, ceq = 0;
#pragma unroll
    for (int i = 0; i < PER_THREAD; ++i) {
        cgt += (key[i] > T) ? 1u : 0u;
        ceq += (key[i] == T) ? 1u : 0u;
    }
    const unsigned n_gt = block_reduce_bcast(cgt, sh_red, lane, warp);
    const unsigned need = K_KEEP - n_gt;  // 1..n_eq by construction

    // ---- stable exclusive scan of equal-counts (global index order) ----
    // thread t owns global elements [t*16, t*16+16), so thread order == index order.
    sh_scan[tid] = ceq;
    __syncthreads();
#pragma unroll 1
    for (int off = 1; off < NTHREADS; off <<= 1) {
        unsigned t = (tid >= off) ? sh_scan[tid - off] : 0u;
        __syncthreads();
        sh_scan[tid] += t;
        __syncthreads();
    }
    unsigned rank = sh_scan[tid] - ceq;  // exclusive prefix of equals

    // ---- emit: keep (> T) always, (== T) only for first `need` by index ----
    float4* outr = reinterpret_cast<float4*>(out + row_base) + tid * 4;
#pragma unroll
    for (int j = 0; j < 4; ++j) {
        float r[4];
#pragma unroll
        for (int c = 0; c < 4; ++c) {
            unsigned k = key[j * 4 + c];
            bool eq = (k == T);
            bool keep = (k > T) || (eq && (rank < need));
            r[c] = keep ? k2f(k) : 0.0f;
            rank += eq ? 1u : 0u;
        }
        float4 o;
        o.x = r[0]; o.y = r[1]; o.z = r[2]; o.w = r[3];
        outr[j] = o;
    }
}

extern "C" void kernel_launch(void* const* d_in, const int* in_sizes, int n_in,
                              void* d_out, int out_size) {
    const float* x = (const float*)d_in[0];
    float* out = (float*)d_out;
    int rows = out_size / D_DIM;   // 16384 for the given shape
    topk_keep_kernel<<<rows, NTHREADS>>>(x, out);
}

// round 2
// speedup vs baseline: 1.4761x; 1.4761x over previous
#include <cuda_runtime.h>
#include <cstdint>

// TopK keep: zero all but the K=512 largest entries per 4096-wide row.
// x: f32[4,4096,4096] -> 16384 rows. One CTA (256 threads) per row.
//
// 3-level radix select on monotonic uint keys: 8-bit digit (per-warp
// privatized histogram + match_any dedup), then two 12-bit digits
// (shared 4096-bin histograms, prefix-predicated). Gives the exact K-th
// largest key T and the exact number `need` of ==T elements to keep
// (lowest index first), matching jax.lax.top_k semantics bit-exactly.

#define D_DIM   4096
#define K_KEEP  512
#define NT      256
#define PT      16   // elements per thread
#define NW      8    // warps per CTA

__device__ __forceinline__ unsigned f2k(float f) {
    unsigned u = __float_as_uint(f);
    return u ^ ((unsigned)((int)u >> 31) | 0x80000000u);
}
__device__ __forceinline__ float k2f(unsigned k) {
    return __uint_as_float(k ^ ((unsigned)((int)(~k) >> 31) | 0x80000000u));
}

__global__ __launch_bounds__(NT, 6)
void topk_keep_kernel(const float* __restrict__ x, float* __restrict__ out)
{
    __shared__ unsigned keys[PT * NT];   // transposed: keys[i*NT + tid]
    __shared__ unsigned hist[4096];
    __shared__ unsigned wsum[NW];
    __shared__ unsigned selb, selk;

    const int tid  = threadIdx.x;
    const int lane = tid & 31;
    const int warp = tid >> 5;
    const size_t row = (size_t)blockIdx.x * D_DIM;

    // ---------------- load, convert, stage transposed in smem ----------------
    const float4* xr = reinterpret_cast<const float4*>(x + row) + tid * 4;
    unsigned k0[PT];
    {
        float4 v0 = xr[0], v1 = xr[1], v2 = xr[2], v3 = xr[3];
        k0[0]=f2k(v0.x);  k0[1]=f2k(v0.y);  k0[2]=f2k(v0.z);  k0[3]=f2k(v0.w);
        k0[4]=f2k(v1.x);  k0[5]=f2k(v1.y);  k0[6]=f2k(v1.z);  k0[7]=f2k(v1.w);
        k0[8]=f2k(v2.x);  k0[9]=f2k(v2.y);  k0[10]=f2k(v2.z); k0[11]=f2k(v2.w);
        k0[12]=f2k(v3.x); k0[13]=f2k(v3.y); k0[14]=f2k(v3.z); k0[15]=f2k(v3.w);
    }
#pragma unroll
    for (int i = 0; i < PT; ++i) keys[i * NT + tid] = k0[i];

    // zero per-warp level-A histograms (8 warps x 256 bins = 2048 words)
    const uint4 z4 = make_uint4(0u, 0u, 0u, 0u);
    reinterpret_cast<uint4*>(hist)[tid]       = z4;
    reinterpret_cast<uint4*>(hist)[tid + 256] = z4;
    __syncthreads();

    // ---------------- level A: digit = key >> 24 (per-warp hist) ----------------
    {
        unsigned* myh = hist + warp * 256;
#pragma unroll
        for (int i = 0; i < PT; ++i) {
            unsigned d = k0[i] >> 24;
            unsigned m = __match_any_sync(0xffffffffu, d);
            if ((m & ((1u << lane) - 1u)) == 0u)          // leader of equal-digit group
                atomicAdd(&myh[d], (unsigned)__popc(m));
        }
    }
    __syncthreads();

    unsigned kth = K_KEEP;
    unsigned b1;
    {
        unsigned cnt = 0;
#pragma unroll
        for (int w = 0; w < NW; ++w) cnt += hist[w * 256 + tid];
        // inclusive suffix scan within warp (lane index == digit ascending)
        unsigned s = cnt;
#pragma unroll
        for (int o = 1; o < 32; o <<= 1) {
            unsigned v = __shfl_down_sync(0xffffffffu, s, o);
            if (lane + o < 32) s += v;
        }
        if (lane == 0) wsum[warp] = s;
        __syncthreads();
        unsigned addh = 0;
#pragma unroll
        for (int w = 0; w < NW; ++w) if (w > warp) addh += wsum[w];
        unsigned Sincl = s + addh;                 // count of keys with digit >= tid
        if (Sincl >= kth && Sincl - cnt < kth) {   // exactly one thread hits
            selb = (unsigned)tid;
            selk = kth - (Sincl - cnt);
        }
        __syncthreads();
        b1  = selb;
        kth = selk;
        __syncthreads();
    }

    // ---------------- level B: digit = (key >> 12) & 0xFFF ----------------
    reinterpret_cast<uint4*>(hist)[tid]       = z4;
    reinterpret_cast<uint4*>(hist)[tid + 256] = z4;
    reinterpret_cast<uint4*>(hist)[tid + 512] = z4;
    reinterpret_cast<uint4*>(hist)[tid + 768] = z4;
    __syncthreads();
#pragma unroll
    for (int i = 0; i < PT; ++i) {
        unsigned k = keys[i * NT + tid];
        if ((k >> 24) == b1)
            atomicAdd(&hist[(k >> 12) & 0xFFFu], 1u);
    }
    __syncthreads();

    unsigned b2;
    {
        const uint4* hv = reinterpret_cast<const uint4*>(hist) + tid * 4;
        uint4 c0 = hv[0], c1 = hv[1], c2 = hv[2], c3 = hv[3];
        unsigned ct = c0.x+c0.y+c0.z+c0.w + c1.x+c1.y+c1.z+c1.w
                    + c2.x+c2.y+c2.z+c2.w + c3.x+c3.y+c3.z+c3.w;
        unsigned s = ct;
#pragma unroll
        for (int o = 1; o < 32; o <<= 1) {
            unsigned v = __shfl_down_sync(0xffffffffu, s, o);
            if (lane + o < 32) s += v;
        }
        if (lane == 0) wsum[warp] = s;
        __syncthreads();
        unsigned addh = 0;
#pragma unroll
        for (int w = 0; w < NW; ++w) if (w > warp) addh += wsum[w];
        unsigned beyond = (s - ct) + addh;         // digits strictly above my 16-bin chunk
        if (beyond < kth && beyond + ct >= kth) {
            unsigned carr[16] = {c0.x,c0.y,c0.z,c0.w, c1.x,c1.y,c1.z,c1.w,
                                 c2.x,c2.y,c2.z,c2.w, c3.x,c3.y,c3.z,c3.w};
            unsigned rb = beyond;
#pragma unroll
            for (int j = 15; j >= 0; --j) {
                unsigned c = carr[j];
                if (rb < kth && rb + c >= kth) { selb = (unsigned)(tid * 16 + j); selk = kth - rb; }
                rb += c;
            }
        }
        __syncthreads();
        b2  = selb;
        kth = selk;
        __syncthreads();
    }

    // ---------------- level C: digit = key & 0xFFF ----------------
    reinterpret_cast<uint4*>(hist)[tid]       = z4;
    reinterpret_cast<uint4*>(hist)[tid + 256] = z4;
    reinterpret_cast<uint4*>(hist)[tid + 512] = z4;
    reinterpret_cast<uint4*>(hist)[tid + 768] = z4;
    __syncthreads();
    {
        const unsigned prefB = (b1 << 12) | b2;
#pragma unroll
        for (int i = 0; i < PT; ++i) {
            unsigned k = keys[i * NT + tid];
            if ((k >> 12) == prefB)
                atomicAdd(&hist[k & 0xFFFu], 1u);
        }
    }
    __syncthreads();

    unsigned b3;
    {
        const uint4* hv = reinterpret_cast<const uint4*>(hist) + tid * 4;
        uint4 c0 = hv[0], c1 = hv[1], c2 = hv[2], c3 = hv[3];
        unsigned ct = c0.x+c0.y+c0.z+c0.w + c1.x+c1.y+c1.z+c1.w
                    + c2.x+c2.y+c2.z+c2.w + c3.x+c3.y+c3.z+c3.w;
        unsigned s = ct;
#pragma unroll
        for (int o = 1; o < 32; o <<= 1) {
            unsigned v = __shfl_down_sync(0xffffffffu, s, o);
            if (lane + o < 32) s += v;
        }
        if (lane == 0) wsum[warp] = s;
        __syncthreads();
        unsigned addh = 0;
#pragma unroll
        for (int w = 0; w < NW; ++w) if (w > warp) addh += wsum[w];
        unsigned beyond = (s - ct) + addh;
        if (beyond < kth && beyond + ct >= kth) {
            unsigned carr[16] = {c0.x,c0.y,c0.z,c0.w, c1.x,c1.y,c1.z,c1.w,
                                 c2.x,c2.y,c2.z,c2.w, c3.x,c3.y,c3.z,c3.w};
            unsigned rb = beyond;
#pragma unroll
            for (int j = 15; j >= 0; --j) {
                unsigned c = carr[j];
                if (rb < kth && rb + c >= kth) { selb = (unsigned)(tid * 16 + j); selk = kth - rb; }
                rb += c;
            }
        }
        __syncthreads();
        b3  = selb;
        kth = selk;
        __syncthreads();
    }

    const unsigned T    = (b1 << 24) | (b2 << 12) | b3;  // exact K-th largest key
    const unsigned need = kth;                           // # of ==T to keep (from lowest index)

    // ---------------- stable rank among ==T elements ----------------
    unsigned ceq = 0;
#pragma unroll
    for (int i = 0; i < PT; ++i) ceq += (keys[i * NT + tid] == T) ? 1u : 0u;
    unsigned p = ceq;
#pragma unroll
    for (int o = 1; o < 32; o <<= 1) {
        unsigned v = __shfl_up_sync(0xffffffffu, p, o);
        if (lane >= o) p += v;
    }
    if (lane == 31) wsum[warp] = p;   // warp total (inclusive at lane 31)
    __syncthreads();
    unsigned woff = 0;
#pragma unroll
    for (int w = 0; w < NW; ++w) if (w < warp) woff += wsum[w];
    unsigned rank = woff + p - ceq;   // exclusive prefix of equals, global index order

    // ---------------- emit ----------------
    float4* outr = reinterpret_cast<float4*>(out + row) + tid * 4;
#pragma unroll
    for (int j = 0; j < 4; ++j) {
        float r[4];
#pragma unroll
        for (int c = 0; c < 4; ++c) {
            unsigned k = keys[(j * 4 + c) * NT + tid];
            bool eq = (k == T);
            bool keep = (k > T) || (eq && (rank < need));
            r[c] = keep ? k2f(k) : 0.0f;
            rank += eq ? 1u : 0u;
        }
        outr[j] = make_float4(r[0], r[1], r[2], r[3]);
    }
}

extern "C" void kernel_launch(void* const* d_in, const int* in_sizes, int n_in,
                              void* d_out, int out_size) {
    const float* x = (const float*)d_in[0];
    float* out = (float*)d_out;
    int rows = out_size / D_DIM;   // 16384
    topk_keep_kernel<<<rows, NT>>>(x, out);
}

// round 3
// speedup vs baseline: 1.5380x; 1.0420x over previous
#include <cuda_runtime.h>
#include <cstdint>

// TopK keep: zero all but the K=512 largest entries per 4096-wide row.
// x: f32[4,4096,4096] -> 16384 rows. One CTA (256 threads) per row.
//
// 3-level radix select (8 + 12 + 12 bits) on monotonic uint keys, with
// keys held in REGISTERS for the whole kernel (no smem key staging).
// Per-level private histograms, zeroed once each. Exact tie handling:
// threshold T plus stable rank keeps the lowest-index ==T elements,
// matching jax.lax.top_k bit-exactly.

#define D_DIM   4096
#define K_KEEP  512
#define NT      256
#define PT      16   // elements per thread (contiguous: tid*16 .. tid*16+15)
#define NW      8    // warps per CTA

__device__ __forceinline__ unsigned f2k(float f) {
    unsigned u = __float_as_uint(f);
    return u ^ ((unsigned)((int)u >> 31) | 0x80000000u);
}
__device__ __forceinline__ float k2f(unsigned k) {
    return __uint_as_float(k ^ ((unsigned)((int)(~k) >> 31) | 0x80000000u));
}

__global__ __launch_bounds__(NT, 4)
void topk_keep_kernel(const float* __restrict__ x, float* __restrict__ out)
{
    __shared__ __align__(16) unsigned histA[2048];  // 8 warps x 256 bins
    __shared__ __align__(16) unsigned histB[4096];
    __shared__ __align__(16) unsigned histC[4096];
    __shared__ unsigned wsum[NW];
    __shared__ unsigned selb, selk;

    const int tid  = threadIdx.x;
    const int lane = tid & 31;
    const int warp = tid >> 5;
    const size_t row = (size_t)blockIdx.x * D_DIM;

    // ---------------- load + convert: keys live in registers ----------------
    const float4* xr = reinterpret_cast<const float4*>(x + row) + tid * 4;
    unsigned k0[PT];
    {
        float4 v0 = xr[0], v1 = xr[1], v2 = xr[2], v3 = xr[3];
        k0[0]=f2k(v0.x);  k0[1]=f2k(v0.y);  k0[2]=f2k(v0.z);  k0[3]=f2k(v0.w);
        k0[4]=f2k(v1.x);  k0[5]=f2k(v1.y);  k0[6]=f2k(v1.z);  k0[7]=f2k(v1.w);
        k0[8]=f2k(v2.x);  k0[9]=f2k(v2.y);  k0[10]=f2k(v2.z); k0[11]=f2k(v2.w);
        k0[12]=f2k(v3.x); k0[13]=f2k(v3.y); k0[14]=f2k(v3.z); k0[15]=f2k(v3.w);
    }

    // ---------------- zero all histograms once (uint4 stores) ----------------
    const uint4 z4 = make_uint4(0u, 0u, 0u, 0u);
    {
        uint4* a = reinterpret_cast<uint4*>(histA);
        uint4* b = reinterpret_cast<uint4*>(histB);
        uint4* c = reinterpret_cast<uint4*>(histC);
        a[tid] = z4;  a[tid + 256] = z4;
        b[tid] = z4;  b[tid + 256] = z4;  b[tid + 512] = z4;  b[tid + 768] = z4;
        c[tid] = z4;  c[tid + 256] = z4;  c[tid + 512] = z4;  c[tid + 768] = z4;
    }
    __syncthreads();

    // ---------------- level A: digit = key >> 24 (per-warp hist + dedup) ----
    {
        unsigned* myh = histA + warp * 256;
#pragma unroll
        for (int i = 0; i < PT; ++i) {
            unsigned d = k0[i] >> 24;
            unsigned m = __match_any_sync(0xffffffffu, d);
            if ((m & ((1u << lane) - 1u)) == 0u)
                atomicAdd(&myh[d], (unsigned)__popc(m));
        }
    }
    __syncthreads();

    unsigned kth = K_KEEP;
    unsigned b1;
    {
        unsigned cnt = 0;
#pragma unroll
        for (int w = 0; w < NW; ++w) cnt += histA[w * 256 + tid];
        unsigned s = cnt;                               // suffix scan in-warp
#pragma unroll
        for (int o = 1; o < 32; o <<= 1) {
            unsigned v = __shfl_down_sync(0xffffffffu, s, o);
            if (lane + o < 32) s += v;
        }
        if (lane == 0) wsum[warp] = s;
        __syncthreads();
        unsigned addh = 0;
#pragma unroll
        for (int w = 0; w < NW; ++w) if (w > warp) addh += wsum[w];
        unsigned Sincl = s + addh;                      // count(digit >= tid)
        if (Sincl >= kth && Sincl - cnt < kth) {
            selb = (unsigned)tid;
            selk = kth - (Sincl - cnt);
        }
        __syncthreads();
        b1  = selb;
        kth = selk;
    }

    // ---------------- level B: digit = (key >> 12) & 0xFFF ----------------
#pragma unroll
    for (int i = 0; i < PT; ++i) {
        unsigned k = k0[i];
        if ((k >> 24) == b1)
            atomicAdd(&histB[(k >> 12) & 0xFFFu], 1u);
    }
    __syncthreads();

    unsigned b2;
    {
        const uint4* hv = reinterpret_cast<const uint4*>(histB) + tid * 4;
        uint4 c0 = hv[0], c1 = hv[1], c2 = hv[2], c3 = hv[3];
        unsigned ct = c0.x+c0.y+c0.z+c0.w + c1.x+c1.y+c1.z+c1.w
                    + c2.x+c2.y+c2.z+c2.w + c3.x+c3.y+c3.z+c3.w;
        unsigned s = ct;
#pragma unroll
        for (int o = 1; o < 32; o <<= 1) {
            unsigned v = __shfl_down_sync(0xffffffffu, s, o);
            if (lane + o < 32) s += v;
        }
        if (lane == 0) wsum[warp] = s;
        __syncthreads();
        unsigned addh = 0;
#pragma unroll
        for (int w = 0; w < NW; ++w) if (w > warp) addh += wsum[w];
        unsigned beyond = (s - ct) + addh;              // digits above my 16 bins
        if (beyond < kth && beyond + ct >= kth) {
            unsigned carr[16] = {c0.x,c0.y,c0.z,c0.w, c1.x,c1.y,c1.z,c1.w,
                                 c2.x,c2.y,c2.z,c2.w, c3.x,c3.y,c3.z,c3.w};
            unsigned rb = beyond;
#pragma unroll
            for (int j = 15; j >= 0; --j) {
                unsigned c = carr[j];
                if (rb < kth && rb + c >= kth) { selb = (unsigned)(tid * 16 + j); selk = kth - rb; }
                rb += c;
            }
        }
        __syncthreads();
        b2  = selb;
        kth = selk;
    }

    // ---------------- level C: digit = key & 0xFFF ----------------
    {
        const unsigned prefB = (b1 << 12) | b2;
#pragma unroll
        for (int i = 0; i < PT; ++i) {
            unsigned k = k0[i];
            if ((k >> 12) == prefB)
                atomicAdd(&histC[k & 0xFFFu], 1u);
        }
    }
    __syncthreads();

    unsigned b3;
    {
        const uint4* hv = reinterpret_cast<const uint4*>(histC) + tid * 4;
        uint4 c0 = hv[0], c1 = hv[1], c2 = hv[2], c3 = hv[3];
        unsigned ct = c0.x+c0.y+c0.z+c0.w + c1.x+c1.y+c1.z+c1.w
                    + c2.x+c2.y+c2.z+c2.w + c3.x+c3.y+c3.z+c3.w;
        unsigned s = ct;
#pragma unroll
        for (int o = 1; o < 32; o <<= 1) {
            unsigned v = __shfl_down_sync(0xffffffffu, s, o);
            if (lane + o < 32) s += v;
        }
        if (lane == 0) wsum[warp] = s;
        __syncthreads();
        unsigned addh = 0;
#pragma unroll
        for (int w = 0; w < NW; ++w) if (w > warp) addh += wsum[w];
        unsigned beyond = (s - ct) + addh;
        if (beyond < kth && beyond + ct >= kth) {
            unsigned carr[16] = {c0.x,c0.y,c0.z,c0.w, c1.x,c1.y,c1.z,c1.w,
                                 c2.x,c2.y,c2.z,c2.w, c3.x,c3.y,c3.z,c3.w};
            unsigned rb = beyond;
#pragma unroll
            for (int j = 15; j >= 0; --j) {
                unsigned c = carr[j];
                if (rb < kth && rb + c >= kth) { selb = (unsigned)(tid * 16 + j); selk = kth - rb; }
                rb += c;
            }
        }
        __syncthreads();
        b3  = selb;
        kth = selk;
        __syncthreads();   // protect wsum before reuse below
    }

    const unsigned T    = (b1 << 24) | (b2 << 12) | b3;  // exact K-th largest key
    const unsigned need = kth;                           // # of ==T kept (lowest index)

    // ---------------- stable rank among ==T elements (register keys) -------
    unsigned ceq = 0;
#pragma unroll
    for (int i = 0; i < PT; ++i) ceq += (k0[i] == T) ? 1u : 0u;
    unsigned p = ceq;
#pragma unroll
    for (int o = 1; o < 32; o <<= 1) {
        unsigned v = __shfl_up_sync(0xffffffffu, p, o);
        if (lane >= o) p += v;
    }
    if (lane == 31) wsum[warp] = p;
    __syncthreads();
    unsigned woff = 0;
#pragma unroll
    for (int w = 0; w < NW; ++w) if (w < warp) woff += wsum[w];
    unsigned rank = woff + p - ceq;   // exclusive prefix of equals, index order

    // ---------------- emit ----------------
    float4* outr = reinterpret_cast<float4*>(out + row) + tid * 4;
#pragma unroll
    for (int j = 0; j < 4; ++j) {
        float r[4];
#pragma unroll
        for (int c = 0; c < 4; ++c) {
            unsigned k = k0[j * 4 + c];
            bool eq = (k == T);
            bool keep = (k > T) || (eq && (rank < need));
            r[c] = keep ? k2f(k) : 0.0f;
            rank += eq ? 1u : 0u;
        }
        outr[j] = make_float4(r[0], r[1], r[2], r[3]);
    }
}

extern "C" void kernel_launch(void* const* d_in, const int* in_sizes, int n_in,
                              void* d_out, int out_size) {
    const float* x = (const float*)d_in[0];
    float* out = (float*)d_out;
    int rows = out_size / D_DIM;   // 16384
    topk_keep_kernel<<<rows, NT>>>(x, out);
}